// round 8
// baseline (speedup 1.0000x reference)
#include <cuda_runtime.h>
#include <cstdint>

#define B_   64
#define T_   4096
#define H_   128
#define C1_  64
#define NCLS_ 40
#define NROWS (B_ * T_)          // 262144
#define NSTAT_BLK 128

// ---------------- device scratch (no allocations allowed) ----------------
__device__ float g_part[NSTAT_BLK * 9];  // per-block partial moments of x
__device__ float g_cw[C1_ * 3];          // conv weights folded with BN scale
__device__ float g_cb[C1_];              // conv bias folded with BN scale+shift

// ---------------- helpers ----------------
__device__ __forceinline__ float sig_fast(float v) {
    return __fdividef(1.f, 1.f + __expf(-v));
}
__device__ __forceinline__ float tanh_fast(float v) {
    return __fdividef(2.f, 1.f + __expf(-2.f * v)) - 1.f;
}
__device__ __forceinline__ uint32_t smem_u32(const void* p) {
    return (uint32_t)__cvta_generic_to_shared(p);
}
__device__ __forceinline__ uint32_t mapa_u32(uint32_t addr, uint32_t rank) {
    uint32_t r;
    asm("mapa.shared::cluster.u32 %0, %1, %2;" : "=r"(r) : "r"(addr), "r"(rank));
    return r;
}
// async store to peer SMEM with tx-completion on the peer's mbarrier.
__device__ __forceinline__ void st_async_remote_f32(uint32_t addr, float v, uint32_t mbar) {
    asm volatile("st.async.shared::cluster.mbarrier::complete_tx::bytes.f32 [%0], %1, [%2];"
                 :: "r"(addr), "f"(v), "r"(mbar) : "memory");
}
__device__ __forceinline__ void mbar_init(uint32_t addr, uint32_t cnt) {
    asm volatile("mbarrier.init.shared.b64 [%0], %1;" :: "r"(addr), "r"(cnt) : "memory");
}
__device__ __forceinline__ void mbar_expect_tx(uint32_t addr, uint32_t bytes) {
    asm volatile("mbarrier.arrive.expect_tx.shared.b64 _, [%0], %1;"
                 :: "r"(addr), "r"(bytes) : "memory");
}
__device__ __forceinline__ void mbar_wait(uint32_t addr, uint32_t parity) {
    asm volatile(
        "{\n\t"
        ".reg .pred P;\n\t"
        "WAITLOOP_%=:\n\t"
        "mbarrier.try_wait.parity.acquire.cta.shared::cta.b64 P, [%0], %1, 0x989680;\n\t"
        "@P bra.uni WAITDONE_%=;\n\t"
        "bra.uni WAITLOOP_%=;\n\t"
        "WAITDONE_%=:\n\t"
        "}\n\t"
        :: "r"(addr), "r"(parity) : "memory");
}
__device__ __forceinline__ void cluster_barrier() {
    asm volatile("barrier.cluster.arrive.aligned;" ::: "memory");
    asm volatile("barrier.cluster.wait.aligned;" ::: "memory");
}
// packed fp32 pair math (sm_103a fma.rn.f32x2)
__device__ __forceinline__ unsigned long long pack2(float lo, float hi) {
    unsigned long long u;
    asm("mov.b64 %0, {%1, %2};" : "=l"(u) : "f"(lo), "f"(hi));
    return u;
}
__device__ __forceinline__ void unpack2(float& lo, float& hi, unsigned long long u) {
    asm("mov.b64 {%0, %1}, %2;" : "=f"(lo), "=f"(hi) : "l"(u));
}
__device__ __forceinline__ void ffma2(unsigned long long& acc, unsigned long long a,
                                      unsigned long long b) {
    asm("fma.rn.f32x2 %0, %1, %2, %3;" : "=l"(acc) : "l"(a), "l"(b), "l"(acc));
}
union F4U2 { float4 v; unsigned long long u[2]; };

// ---------------- kernel 1: second moments of x over (B,T) ----------------
__global__ void __launch_bounds__(256) stats_kernel(const float* __restrict__ x) {
    __shared__ float red[256];
    float s0=0,s1=0,s2=0,s3=0,s4=0,s5=0,s6=0,s7=0,s8=0;
    const int stride = NSTAT_BLK * 256;
    for (int i = blockIdx.x * 256 + threadIdx.x; i < NROWS; i += stride) {
        float a = x[i*3+0], b = x[i*3+1], c = x[i*3+2];
        s0 += a;   s1 += b;   s2 += c;
        s3 += a*a; s4 += a*b; s5 += a*c;
        s6 += b*b; s7 += b*c; s8 += c*c;
    }
    float sv[9] = {s0,s1,s2,s3,s4,s5,s6,s7,s8};
    #pragma unroll 1
    for (int j = 0; j < 9; j++) {
        red[threadIdx.x] = sv[j];
        __syncthreads();
        for (int o = 128; o > 0; o >>= 1) {
            if (threadIdx.x < o) red[threadIdx.x] += red[threadIdx.x + o];
            __syncthreads();
        }
        if (threadIdx.x == 0) g_part[blockIdx.x * 9 + j] = red[0];
        __syncthreads();
    }
}

// ---------------- kernel 2: fold BN (derived analytically) into conv ----------------
__global__ void __launch_bounds__(64) fold_kernel(const float* __restrict__ conv_w,
                                                  const float* __restrict__ conv_b,
                                                  const float* __restrict__ gamma,
                                                  const float* __restrict__ beta) {
    __shared__ float st[9];
    if (threadIdx.x < 9) {
        float s = 0.f;
        for (int i = 0; i < NSTAT_BLK; i++) s += g_part[i * 9 + threadIdx.x];
        st[threadIdx.x] = s;
    }
    __syncthreads();
    const int c = threadIdx.x;
    const float N = (float)NROWS;
    float m0 = st[0]/N, m1 = st[1]/N, m2 = st[2]/N;
    float C00 = st[3]/N - m0*m0, C01 = st[4]/N - m0*m1, C02 = st[5]/N - m0*m2;
    float C11 = st[6]/N - m1*m1, C12 = st[7]/N - m1*m2, C22 = st[8]/N - m2*m2;
    float w0 = conv_w[c*3+0], w1 = conv_w[c*3+1], w2 = conv_w[c*3+2];
    float mean = w0*m0 + w1*m1 + w2*m2 + conv_b[c];
    float var  = w0*w0*C00 + w1*w1*C11 + w2*w2*C22
               + 2.f*(w0*w1*C01 + w0*w2*C02 + w1*w2*C12);
    float sc = gamma[c] * rsqrtf(var + 1e-5f);
    g_cw[c*3+0] = w0 * sc;
    g_cw[c*3+1] = w1 * sc;
    g_cw[c*3+2] = w2 * sc;
    g_cb[c]     = conv_b[c] * sc + (beta[c] - mean * sc);
}

// ---------------- kernel 3: persistent clustered LSTM, 2 batch rows/cluster ----------------
// 64 CTAs, cluster=(2,1,1): cluster cid = blockIdx.x>>1 owns batch rows 2cid, 2cid+1.
// half = blockIdx.x&1 owns hidden units [half*64, half*64+64).
// Thread owns ONE gate row r (weights in registers, shared by both batch rows) and
// accumulates gates for BOTH rows per step — row B's FMA stream hides row A's
// exchange/activation latency chain (and vice versa).
__global__ void __cluster_dims__(2, 1, 1) __launch_bounds__(256, 1)
lstm_kernel(const float* __restrict__ x,
            const float* __restrict__ w_ih, const float* __restrict__ b_ih,
            const float* __restrict__ w_hh, const float* __restrict__ b_hh,
            const float* __restrict__ out_w, const float* __restrict__ out_b,
            const float* __restrict__ h0, const float* __restrict__ c0,
            float* __restrict__ out) {
    __shared__ __align__(16) float h_s[2][2][H_];  // [row][buf][128]
    __shared__ float c_s[2][64];                   // [row][own half]
    __shared__ __align__(16) float y_s[2][C1_];    // [row][64]
    __shared__ float act_s[2][256];                // [row][gate row of this CTA]
    __shared__ __align__(8) unsigned long long mbar[1];

    const int tid  = threadIdx.x;
    const int cid  = blockIdx.x >> 1;
    const int half = blockIdx.x & 1;
    const int bA   = 2 * cid;
    const int bB   = 2 * cid + 1;
    const int q    = tid >> 6;        // gate: 0=i 1=f 2=g 3=o
    const int jj   = tid & 63;        // hidden index within half
    const int r    = q * H_ + half * 64 + jj;   // global gate row in [0,512)

    // pack weights into f32x2 register pairs (one-time; shared by both rows)
    unsigned long long whh2[H_ / 2];
    #pragma unroll
    for (int k = 0; k < H_ / 2; k++) {
        float2 w = ((const float2*)(w_hh + (size_t)r * H_))[k];
        whh2[k] = pack2(w.x, w.y);
    }
    unsigned long long wih2[C1_ / 2];
    #pragma unroll
    for (int k = 0; k < C1_ / 2; k++) {
        float2 w = ((const float2*)(w_ih + (size_t)r * C1_))[k];
        wih2[k] = pack2(w.x, w.y);
    }
    const float bias = b_ih[r] + b_hh[r];

    // state init
    if (tid < H_)                 h_s[0][0][tid]        = h0[bA * H_ + tid];
    else                          h_s[1][0][tid - H_]   = h0[bB * H_ + (tid - H_)];
    if (tid < 64)                 c_s[0][tid]       = c0[bA * H_ + half * 64 + tid];
    else if (tid < 128)           c_s[1][tid - 64]  = c0[bB * H_ + half * 64 + (tid - 64)];

    const float* xA = x + (size_t)bA * T_ * 3;
    const float* xB = x + (size_t)bB * T_ * 3;
    if (tid >= 128 && tid < 192) {          // y_A(0)
        int ch = tid - 128;
        float v = fmaf(g_cw[ch*3+2], xA[2],
                  fmaf(g_cw[ch*3+1], xA[1],
                  fmaf(g_cw[ch*3+0], xA[0], g_cb[ch])));
        y_s[0][ch] = fmaxf(v, 0.f);
    } else if (tid >= 192) {                // y_B(0)
        int ch = tid - 192;
        float v = fmaf(g_cw[ch*3+2], xB[2],
                  fmaf(g_cw[ch*3+1], xB[1],
                  fmaf(g_cw[ch*3+0], xB[0], g_cb[ch])));
        y_s[1][ch] = fmaxf(v, 0.f);
    }

    const uint32_t mbar_a    = smem_u32(mbar);
    const uint32_t peer_mbar = mapa_u32(mbar_a, (uint32_t)(half ^ 1));
    const uint32_t peer_h    = mapa_u32(smem_u32(&h_s[0][0][0]), (uint32_t)(half ^ 1));

    if (tid == 0) mbar_init(mbar_a, 1);
    __syncthreads();
    cluster_barrier();   // mbar init visible cluster-wide before any st.async
    if (tid == 0) mbar_expect_tx(mbar_a, 2 * 64 * 4);   // phase 0: both rows' halves

    uint32_t parity = 0;
    const float* xpA = xA + 3;
    const float* xpB = xB + 3;

    #pragma unroll 1
    for (int t = 0; t < T_; t++) {
        // ---- input-side partial gates for BOTH rows (independent of h) ----
        unsigned long long aA0 = pack2(bias, 0.f), aA1 = pack2(0.f, 0.f);
        unsigned long long aB0 = pack2(bias, 0.f), aB1 = pack2(0.f, 0.f);
        const float4* yA4 = (const float4*)y_s[0];
        const float4* yB4 = (const float4*)y_s[1];
        #pragma unroll
        for (int c2 = 0; c2 < C1_ / 4; c2++) {
            F4U2 ya; ya.v = yA4[c2];
            F4U2 yb; yb.v = yB4[c2];
            ffma2(aA0, wih2[2*c2],     ya.u[0]);
            ffma2(aA1, wih2[2*c2 + 1], ya.u[1]);
            ffma2(aB0, wih2[2*c2],     yb.u[0]);
            ffma2(aB1, wih2[2*c2 + 1], yb.u[1]);
        }
        // prefetch x(t+1) for the conv threads
        float px0 = 0.f, px1 = 0.f, px2 = 0.f;
        const bool doyA = (tid >= 128 && tid < 192 && t < T_ - 1);
        const bool doyB = (tid >= 192 && t < T_ - 1);
        if (doyA) { px0 = xpA[0]; px1 = xpA[1]; px2 = xpA[2]; }
        else if (doyB) { px0 = xpB[0]; px1 = xpB[1]; px2 = xpB[2]; }

        // ---- wait for peer halves of h(t) (both rows); re-arm for next phase ----
        if (t > 0) {
            mbar_wait(mbar_a, parity);
            parity ^= 1;
            if (tid == 0) mbar_expect_tx(mbar_a, 2 * 64 * 4);
        }
        const int cur = t & 1;
        const float4* hA4 = (const float4*)h_s[0][cur];
        const float4* hB4 = (const float4*)h_s[1][cur];
        #pragma unroll
        for (int k2 = 0; k2 < H_ / 4; k2++) {
            F4U2 ha; ha.v = hA4[k2];
            F4U2 hb; hb.v = hB4[k2];
            ffma2(aA0, whh2[2*k2],     ha.u[0]);
            ffma2(aA1, whh2[2*k2 + 1], ha.u[1]);
            ffma2(aB0, whh2[2*k2],     hb.u[0]);
            ffma2(aB1, whh2[2*k2 + 1], hb.u[1]);
        }
        {
            float l0, h0f, l1, h1f;
            unpack2(l0, h0f, aA0); unpack2(l1, h1f, aA1);
            float ga = (l0 + l1) + (h0f + h1f);
            ga = (q == 2) ? tanh_fast(ga) : sig_fast(ga);
            act_s[0][tid] = ga;
            unpack2(l0, h0f, aB0); unpack2(l1, h1f, aB1);
            float gb = (l0 + l1) + (h0f + h1f);
            gb = (q == 2) ? tanh_fast(gb) : sig_fast(gb);
            act_s[1][tid] = gb;
        }
        __syncthreads();

        const int nxt = cur ^ 1;
        if (tid < 128) {
            // c/h update: tid<64 -> row A, tid in [64,128) -> row B (parallel chains)
            const int row = tid >> 6;
            const int j   = tid & 63;
            const float* ar = act_s[row];
            float cc = fmaf(ar[64 + j], c_s[row][j], ar[j] * ar[128 + j]);
            c_s[row][j] = cc;
            float hn = ar[192 + j] * tanh_fast(cc);
            int hj = half * 64 + j;
            h_s[row][nxt][hj] = hn;
            st_async_remote_f32(peer_h + (uint32_t)(((row * 2 + nxt) * H_) + hj) * 4u,
                                hn, peer_mbar);
        } else if (doyA) {
            int ch = tid - 128;
            float v = fmaf(g_cw[ch*3+2], px2,
                      fmaf(g_cw[ch*3+1], px1,
                      fmaf(g_cw[ch*3+0], px0, g_cb[ch])));
            y_s[0][ch] = fmaxf(v, 0.f);
        } else if (doyB) {
            int ch = tid - 192;
            float v = fmaf(g_cw[ch*3+2], px2,
                      fmaf(g_cw[ch*3+1], px1,
                      fmaf(g_cw[ch*3+0], px0, g_cb[ch])));
            y_s[1][ch] = fmaxf(v, 0.f);
        }
        __syncthreads();
        xpA += 3; xpB += 3;
    }

    // final exchange: h(T) complete in buffer 0 (T even)
    mbar_wait(mbar_a, parity);

    if (half == 0) {
        if (tid < NCLS_) {
            float acc = out_b[tid];
            #pragma unroll 4
            for (int k = 0; k < H_; k++)
                acc = fmaf(h_s[0][0][k], out_w[tid * H_ + k], acc);
            out[bA * NCLS_ + tid] = acc;
        } else if (tid >= 64 && tid < 64 + NCLS_) {
            int o = tid - 64;
            float acc = out_b[o];
            #pragma unroll 4
            for (int k = 0; k < H_; k++)
                acc = fmaf(h_s[1][0][k], out_w[o * H_ + k], acc);
            out[bB * NCLS_ + o] = acc;
        }
    }
    cluster_barrier();   // clean cluster teardown
}

// ---------------- launch ----------------
extern "C" void kernel_launch(void* const* d_in, const int* in_sizes, int n_in,
                              void* d_out, int out_size) {
    const float* x      = (const float*)d_in[0];
    const float* conv_w = (const float*)d_in[1];
    const float* conv_b = (const float*)d_in[2];
    const float* bn_g   = (const float*)d_in[3];
    const float* bn_b   = (const float*)d_in[4];
    const float* w_ih   = (const float*)d_in[5];
    const float* b_ih   = (const float*)d_in[6];
    const float* w_hh   = (const float*)d_in[7];
    const float* b_hh   = (const float*)d_in[8];
    const float* out_w  = (const float*)d_in[9];
    const float* out_b  = (const float*)d_in[10];
    const float* h0     = (const float*)d_in[11];
    const float* c0     = (const float*)d_in[12];
    float* out = (float*)d_out;

    stats_kernel<<<NSTAT_BLK, 256>>>(x);
    fold_kernel<<<1, 64>>>(conv_w, conv_b, bn_g, bn_b);
    lstm_kernel<<<B_, 256>>>(x, w_ih, b_ih, w_hh, b_hh,
                             out_w, out_b, h0, c0, out);
}

// round 9
// speedup vs baseline: 1.1027x; 1.1027x over previous
#include <cuda_runtime.h>
#include <cstdint>

#define B_   64
#define T_   4096
#define H_   128
#define C1_  64
#define NCLS_ 40
#define NROWS (B_ * T_)          // 262144
#define NSTAT_BLK 128

// ---------------- device scratch (no allocations allowed) ----------------
__device__ float g_part[NSTAT_BLK * 9];  // per-block partial moments of x
__device__ float g_cw[C1_ * 3];          // conv weights folded with BN scale
__device__ float g_cb[C1_];              // conv bias folded with BN scale+shift

// ---------------- helpers ----------------
__device__ __forceinline__ float sig_fast(float v) {
    return __fdividef(1.f, 1.f + __expf(-v));
}
__device__ __forceinline__ float tanh_fast(float v) {
    return __fdividef(2.f, 1.f + __expf(-2.f * v)) - 1.f;
}
__device__ __forceinline__ uint32_t smem_u32(const void* p) {
    return (uint32_t)__cvta_generic_to_shared(p);
}
__device__ __forceinline__ uint32_t mapa_u32(uint32_t addr, uint32_t rank) {
    uint32_t r;
    asm("mapa.shared::cluster.u32 %0, %1, %2;" : "=r"(r) : "r"(addr), "r"(rank));
    return r;
}
// async store to peer SMEM with tx-completion on the peer's mbarrier.
__device__ __forceinline__ void st_async_remote_f32(uint32_t addr, float v, uint32_t mbar) {
    asm volatile("st.async.shared::cluster.mbarrier::complete_tx::bytes.f32 [%0], %1, [%2];"
                 :: "r"(addr), "f"(v), "r"(mbar) : "memory");
}
__device__ __forceinline__ void mbar_init(uint32_t addr, uint32_t cnt) {
    asm volatile("mbarrier.init.shared.b64 [%0], %1;" :: "r"(addr), "r"(cnt) : "memory");
}
__device__ __forceinline__ void mbar_expect_tx(uint32_t addr, uint32_t bytes) {
    asm volatile("mbarrier.arrive.expect_tx.shared.b64 _, [%0], %1;"
                 :: "r"(addr), "r"(bytes) : "memory");
}
__device__ __forceinline__ void mbar_wait(uint32_t addr, uint32_t parity) {
    asm volatile(
        "{\n\t"
        ".reg .pred P;\n\t"
        "WAITLOOP_%=:\n\t"
        "mbarrier.try_wait.parity.acquire.cta.shared::cta.b64 P, [%0], %1, 0x989680;\n\t"
        "@P bra.uni WAITDONE_%=;\n\t"
        "bra.uni WAITLOOP_%=;\n\t"
        "WAITDONE_%=:\n\t"
        "}\n\t"
        :: "r"(addr), "r"(parity) : "memory");
}
__device__ __forceinline__ void cluster_barrier() {
    asm volatile("barrier.cluster.arrive.aligned;" ::: "memory");
    asm volatile("barrier.cluster.wait.aligned;" ::: "memory");
}
// packed fp32 pair math (sm_103a fma.rn.f32x2)
__device__ __forceinline__ unsigned long long pack2(float lo, float hi) {
    unsigned long long u;
    asm("mov.b64 %0, {%1, %2};" : "=l"(u) : "f"(lo), "f"(hi));
    return u;
}
__device__ __forceinline__ void unpack2(float& lo, float& hi, unsigned long long u) {
    asm("mov.b64 {%0, %1}, %2;" : "=f"(lo), "=f"(hi) : "l"(u));
}
__device__ __forceinline__ void ffma2(unsigned long long& acc, unsigned long long a,
                                      unsigned long long b) {
    asm("fma.rn.f32x2 %0, %1, %2, %3;" : "=l"(acc) : "l"(a), "l"(b), "l"(acc));
}
union F4U2 { float4 v; unsigned long long u[2]; };

// ---------------- kernel 1: second moments of x over (B,T) ----------------
__global__ void __launch_bounds__(256) stats_kernel(const float* __restrict__ x) {
    __shared__ float red[256];
    float s0=0,s1=0,s2=0,s3=0,s4=0,s5=0,s6=0,s7=0,s8=0;
    const int stride = NSTAT_BLK * 256;
    for (int i = blockIdx.x * 256 + threadIdx.x; i < NROWS; i += stride) {
        float a = x[i*3+0], b = x[i*3+1], c = x[i*3+2];
        s0 += a;   s1 += b;   s2 += c;
        s3 += a*a; s4 += a*b; s5 += a*c;
        s6 += b*b; s7 += b*c; s8 += c*c;
    }
    float sv[9] = {s0,s1,s2,s3,s4,s5,s6,s7,s8};
    #pragma unroll 1
    for (int j = 0; j < 9; j++) {
        red[threadIdx.x] = sv[j];
        __syncthreads();
        for (int o = 128; o > 0; o >>= 1) {
            if (threadIdx.x < o) red[threadIdx.x] += red[threadIdx.x + o];
            __syncthreads();
        }
        if (threadIdx.x == 0) g_part[blockIdx.x * 9 + j] = red[0];
        __syncthreads();
    }
}

// ---------------- kernel 2: fold BN (derived analytically) into conv ----------------
__global__ void __launch_bounds__(64) fold_kernel(const float* __restrict__ conv_w,
                                                  const float* __restrict__ conv_b,
                                                  const float* __restrict__ gamma,
                                                  const float* __restrict__ beta) {
    __shared__ float st[9];
    if (threadIdx.x < 9) {
        float s = 0.f;
        for (int i = 0; i < NSTAT_BLK; i++) s += g_part[i * 9 + threadIdx.x];
        st[threadIdx.x] = s;
    }
    __syncthreads();
    const int c = threadIdx.x;
    const float N = (float)NROWS;
    float m0 = st[0]/N, m1 = st[1]/N, m2 = st[2]/N;
    float C00 = st[3]/N - m0*m0, C01 = st[4]/N - m0*m1, C02 = st[5]/N - m0*m2;
    float C11 = st[6]/N - m1*m1, C12 = st[7]/N - m1*m2, C22 = st[8]/N - m2*m2;
    float w0 = conv_w[c*3+0], w1 = conv_w[c*3+1], w2 = conv_w[c*3+2];
    float mean = w0*m0 + w1*m1 + w2*m2 + conv_b[c];
    float var  = w0*w0*C00 + w1*w1*C11 + w2*w2*C22
               + 2.f*(w0*w1*C01 + w0*w2*C02 + w1*w2*C12);
    float sc = gamma[c] * rsqrtf(var + 1e-5f);
    g_cw[c*3+0] = w0 * sc;
    g_cw[c*3+1] = w1 * sc;
    g_cw[c*3+2] = w2 * sc;
    g_cb[c]     = conv_b[c] * sc + (beta[c] - mean * sc);
}

// ---------------- kernel 3: persistent clustered LSTM ----------------
// 128 CTAs, cluster=(2,1,1): blockIdx.x>>1 = batch row, blockIdx.x&1 = hidden half.
// QUAD layout: q = tid&3 (gate i/f/g/o), jj = tid>>2 (hidden unit within half).
// The 4 gates of unit jj live in 4 ADJACENT LANES of one warp -> gate gather is
// 4 shfl (no smem/barrier), c lives in registers (quad-redundant).
// W_hh matmul is split: own-half + W_ih*y issue BEFORE the mbarrier wait
// (inside the peer-exchange flight shadow); only the peer-half is post-wait.
__global__ void __cluster_dims__(2, 1, 1) __launch_bounds__(256, 1)
lstm_kernel(const float* __restrict__ x,
            const float* __restrict__ w_ih, const float* __restrict__ b_ih,
            const float* __restrict__ w_hh, const float* __restrict__ b_hh,
            const float* __restrict__ out_w, const float* __restrict__ out_b,
            const float* __restrict__ h0, const float* __restrict__ c0,
            float* __restrict__ out) {
    __shared__ __align__(16) float h_s[2][H_];   // double-buffered full h
    __shared__ __align__(16) float y_s[C1_];     // conv/BN/relu output, current step
    __shared__ __align__(8) unsigned long long mbar[1];

    const int tid  = threadIdx.x;
    const int b    = blockIdx.x >> 1;
    const int half = blockIdx.x & 1;
    const int q    = tid & 3;         // gate: 0=i 1=f 2=g 3=o
    const int jj   = tid >> 2;        // hidden unit within half [0,64)
    const int r    = q * H_ + half * 64 + jj;   // global gate row in [0,512)
    const int lane = tid & 31;
    const int qb   = lane & ~3;       // quad base lane

    // pack weights into f32x2 register pairs (one-time)
    unsigned long long whh2[H_ / 2];
    #pragma unroll
    for (int k = 0; k < H_ / 2; k++) {
        float2 w = ((const float2*)(w_hh + (size_t)r * H_))[k];
        whh2[k] = pack2(w.x, w.y);
    }
    unsigned long long wih2[C1_ / 2];
    #pragma unroll
    for (int k = 0; k < C1_ / 2; k++) {
        float2 w = ((const float2*)(w_ih + (size_t)r * C1_))[k];
        wih2[k] = pack2(w.x, w.y);
    }
    const float bias = b_ih[r] + b_hh[r];

    // state init: c replicated in all 4 lanes of the quad (registers only)
    float creg = c0[b * H_ + half * 64 + jj];
    if (tid < H_) h_s[0][tid] = h0[b * H_ + tid];

    const float* xb = x + (size_t)b * T_ * 3;
    if (q == 1) {   // y(0): 64 q==1 lanes, channel jj
        float v = fmaf(g_cw[jj*3+2], xb[2],
                  fmaf(g_cw[jj*3+1], xb[1],
                  fmaf(g_cw[jj*3+0], xb[0], g_cb[jj])));
        y_s[jj] = fmaxf(v, 0.f);
    }

    const uint32_t mbar_a    = smem_u32(mbar);
    const uint32_t peer_mbar = mapa_u32(mbar_a, (uint32_t)(half ^ 1));
    const uint32_t peer_h    = mapa_u32(smem_u32(&h_s[0][0]), (uint32_t)(half ^ 1));
    const int own_off  = half * 64;          // own half offset in h
    const int peer_off = own_off ^ 64;       // peer half offset

    if (tid == 0) mbar_init(mbar_a, 1);
    __syncthreads();
    cluster_barrier();   // mbar init visible cluster-wide before any st.async
    if (tid == 0) mbar_expect_tx(mbar_a, 64 * 4);   // phase 0

    uint32_t parity = 0;
    const float* xp = xb + 3;

    #pragma unroll 1
    for (int t = 0; t < T_; t++) {
        const int cur = t & 1;
        // ---- pre-wait: bias + W_ih*y(t) + W_hh_own*h_own(t) (no peer dep) ----
        unsigned long long acc0 = pack2(bias, 0.f), acc1 = pack2(0.f, 0.f);
        const float4* y4 = (const float4*)y_s;
        #pragma unroll
        for (int c2 = 0; c2 < C1_ / 4; c2++) {
            F4U2 yv; yv.v = y4[c2];
            ffma2(acc0, wih2[2*c2],     yv.u[0]);
            ffma2(acc1, wih2[2*c2 + 1], yv.u[1]);
        }
        const float4* ho4 = (const float4*)&h_s[cur][own_off];
        const unsigned long long* who2 = &whh2[own_off / 2];
        #pragma unroll
        for (int k2 = 0; k2 < 16; k2++) {
            F4U2 hv; hv.v = ho4[k2];
            ffma2(acc0, who2[2*k2],     hv.u[0]);
            ffma2(acc1, who2[2*k2 + 1], hv.u[1]);
        }
        // prefetch x(t+1) for the conv lanes
        float px0 = 0.f, px1 = 0.f, px2 = 0.f;
        const bool doy = (q == 1) && (t < T_ - 1);
        if (doy) { px0 = xp[0]; px1 = xp[1]; px2 = xp[2]; }

        // ---- wait for peer half of h(t); re-arm for next phase ----
        if (t > 0) {
            mbar_wait(mbar_a, parity);
            parity ^= 1;
            if (tid == 0) mbar_expect_tx(mbar_a, 64 * 4);
        }
        const float4* hp4 = (const float4*)&h_s[cur][peer_off];
        const unsigned long long* whp2 = &whh2[peer_off / 2];
        #pragma unroll
        for (int k2 = 0; k2 < 16; k2++) {
            F4U2 hv; hv.v = hp4[k2];
            ffma2(acc0, whp2[2*k2],     hv.u[0]);
            ffma2(acc1, whp2[2*k2 + 1], hv.u[1]);
        }
        float l0, hh0, l1, hh1;
        unpack2(l0, hh0, acc0);
        unpack2(l1, hh1, acc1);
        float a = (l0 + l1) + (hh0 + hh1);
        a = (q == 2) ? tanh_fast(a) : sig_fast(a);

        // ---- quad gate gather via shfl (same warp, adjacent lanes) ----
        float gi = __shfl_sync(0xFFFFFFFFu, a, qb + 0);
        float gf = __shfl_sync(0xFFFFFFFFu, a, qb + 1);
        float gg = __shfl_sync(0xFFFFFFFFu, a, qb + 2);
        float go = __shfl_sync(0xFFFFFFFFu, a, qb + 3);
        creg = fmaf(gf, creg, gi * gg);
        float hn = go * tanh_fast(creg);

        const int nxt = cur ^ 1;
        const int hj  = own_off + jj;
        if (q == 0) {
            h_s[nxt][hj] = hn;
            st_async_remote_f32(peer_h + (uint32_t)(nxt * H_ + hj) * 4u, hn, peer_mbar);
        } else if (doy) {
            float v = fmaf(g_cw[jj*3+2], px2,
                      fmaf(g_cw[jj*3+1], px1,
                      fmaf(g_cw[jj*3+0], px0, g_cb[jj])));
            y_s[jj] = fmaxf(v, 0.f);
        }
        __syncthreads();   // local h own-half + y(t+1) visibility for next step
        xp += 3;
    }

    // final: h(T) lands in buffer 0 (T even); wait for peer half
    mbar_wait(mbar_a, parity);

    if (half == 0 && tid < NCLS_) {
        float acc = out_b[tid];
        #pragma unroll 4
        for (int k = 0; k < H_; k++)
            acc = fmaf(h_s[0][k], out_w[tid * H_ + k], acc);
        out[b * NCLS_ + tid] = acc;
    }
    cluster_barrier();   // clean cluster teardown
}

// ---------------- launch ----------------
extern "C" void kernel_launch(void* const* d_in, const int* in_sizes, int n_in,
                              void* d_out, int out_size) {
    const float* x      = (const float*)d_in[0];
    const float* conv_w = (const float*)d_in[1];
    const float* conv_b = (const float*)d_in[2];
    const float* bn_g   = (const float*)d_in[3];
    const float* bn_b   = (const float*)d_in[4];
    const float* w_ih   = (const float*)d_in[5];
    const float* b_ih   = (const float*)d_in[6];
    const float* w_hh   = (const float*)d_in[7];
    const float* b_hh   = (const float*)d_in[8];
    const float* out_w  = (const float*)d_in[9];
    const float* out_b  = (const float*)d_in[10];
    const float* h0     = (const float*)d_in[11];
    const float* c0     = (const float*)d_in[12];
    float* out = (float*)d_out;

    stats_kernel<<<NSTAT_BLK, 256>>>(x);
    fold_kernel<<<1, 64>>>(conv_w, conv_b, bn_g, bn_b);
    lstm_kernel<<<2 * B_, 256>>>(x, w_ih, b_ih, w_hh, b_hh,
                                 out_w, out_b, h0, c0, out);
}

// round 10
// speedup vs baseline: 1.7370x; 1.5753x over previous
#include <cuda_runtime.h>
#include <cstdint>

#define B_   64
#define T_   4096
#define H_   128
#define C1_  64
#define NCLS_ 40
#define NROWS (B_ * T_)          // 262144
#define NSTAT_BLK 128

// ---------------- device scratch (no allocations allowed) ----------------
__device__ float g_part[NSTAT_BLK * 9];  // per-block partial moments of x
__device__ float g_cw[C1_ * 3];          // conv weights folded with BN scale
__device__ float g_cb[C1_];              // conv bias folded with BN scale+shift

// ---------------- helpers ----------------
__device__ __forceinline__ float tanh_fast(float v) {
    return __fdividef(2.f, 1.f + __expf(-2.f * v)) - 1.f;
}
__device__ __forceinline__ uint32_t smem_u32(const void* p) {
    return (uint32_t)__cvta_generic_to_shared(p);
}
__device__ __forceinline__ uint32_t mapa_u32(uint32_t addr, uint32_t rank) {
    uint32_t r;
    asm("mapa.shared::cluster.u32 %0, %1, %2;" : "=r"(r) : "r"(addr), "r"(rank));
    return r;
}
// async store to peer SMEM with tx-completion on the peer's mbarrier.
__device__ __forceinline__ void st_async_remote_f32(uint32_t addr, float v, uint32_t mbar) {
    asm volatile("st.async.shared::cluster.mbarrier::complete_tx::bytes.f32 [%0], %1, [%2];"
                 :: "r"(addr), "f"(v), "r"(mbar) : "memory");
}
__device__ __forceinline__ void mbar_init(uint32_t addr, uint32_t cnt) {
    asm volatile("mbarrier.init.shared.b64 [%0], %1;" :: "r"(addr), "r"(cnt) : "memory");
}
__device__ __forceinline__ void mbar_expect_tx(uint32_t addr, uint32_t bytes) {
    asm volatile("mbarrier.arrive.expect_tx.shared.b64 _, [%0], %1;"
                 :: "r"(addr), "r"(bytes) : "memory");
}
__device__ __forceinline__ void mbar_wait(uint32_t addr, uint32_t parity) {
    asm volatile(
        "{\n\t"
        ".reg .pred P;\n\t"
        "WAITLOOP_%=:\n\t"
        "mbarrier.try_wait.parity.acquire.cta.shared::cta.b64 P, [%0], %1, 0x989680;\n\t"
        "@P bra.uni WAITDONE_%=;\n\t"
        "bra.uni WAITLOOP_%=;\n\t"
        "WAITDONE_%=:\n\t"
        "}\n\t"
        :: "r"(addr), "r"(parity) : "memory");
}
__device__ __forceinline__ void cluster_barrier() {
    asm volatile("barrier.cluster.arrive.aligned;" ::: "memory");
    asm volatile("barrier.cluster.wait.aligned;" ::: "memory");
}
// packed fp32 pair math (sm_103a fma.rn.f32x2)
__device__ __forceinline__ unsigned long long pack2(float lo, float hi) {
    unsigned long long u;
    asm("mov.b64 %0, {%1, %2};" : "=l"(u) : "f"(lo), "f"(hi));
    return u;
}
__device__ __forceinline__ void unpack2(float& lo, float& hi, unsigned long long u) {
    asm("mov.b64 {%0, %1}, %2;" : "=f"(lo), "=f"(hi) : "l"(u));
}
__device__ __forceinline__ void ffma2(unsigned long long& acc, unsigned long long a,
                                      unsigned long long b) {
    asm("fma.rn.f32x2 %0, %1, %2, %3;" : "=l"(acc) : "l"(a), "l"(b), "l"(acc));
}
union F4U2 { float4 v; unsigned long long u[2]; };

// ---------------- kernel 1: second moments of x over (B,T) ----------------
__global__ void __launch_bounds__(256) stats_kernel(const float* __restrict__ x) {
    __shared__ float red[256];
    float s0=0,s1=0,s2=0,s3=0,s4=0,s5=0,s6=0,s7=0,s8=0;
    const int stride = NSTAT_BLK * 256;
    for (int i = blockIdx.x * 256 + threadIdx.x; i < NROWS; i += stride) {
        float a = x[i*3+0], b = x[i*3+1], c = x[i*3+2];
        s0 += a;   s1 += b;   s2 += c;
        s3 += a*a; s4 += a*b; s5 += a*c;
        s6 += b*b; s7 += b*c; s8 += c*c;
    }
    float sv[9] = {s0,s1,s2,s3,s4,s5,s6,s7,s8};
    #pragma unroll 1
    for (int j = 0; j < 9; j++) {
        red[threadIdx.x] = sv[j];
        __syncthreads();
        for (int o = 128; o > 0; o >>= 1) {
            if (threadIdx.x < o) red[threadIdx.x] += red[threadIdx.x + o];
            __syncthreads();
        }
        if (threadIdx.x == 0) g_part[blockIdx.x * 9 + j] = red[0];
        __syncthreads();
    }
}

// ---------------- kernel 2: fold BN (derived analytically) into conv ----------------
__global__ void __launch_bounds__(64) fold_kernel(const float* __restrict__ conv_w,
                                                  const float* __restrict__ conv_b,
                                                  const float* __restrict__ gamma,
                                                  const float* __restrict__ beta) {
    __shared__ float st[9];
    if (threadIdx.x < 9) {
        float s = 0.f;
        for (int i = 0; i < NSTAT_BLK; i++) s += g_part[i * 9 + threadIdx.x];
        st[threadIdx.x] = s;
    }
    __syncthreads();
    const int c = threadIdx.x;
    const float N = (float)NROWS;
    float m0 = st[0]/N, m1 = st[1]/N, m2 = st[2]/N;
    float C00 = st[3]/N - m0*m0, C01 = st[4]/N - m0*m1, C02 = st[5]/N - m0*m2;
    float C11 = st[6]/N - m1*m1, C12 = st[7]/N - m1*m2, C22 = st[8]/N - m2*m2;
    float w0 = conv_w[c*3+0], w1 = conv_w[c*3+1], w2 = conv_w[c*3+2];
    float mean = w0*m0 + w1*m1 + w2*m2 + conv_b[c];
    float var  = w0*w0*C00 + w1*w1*C11 + w2*w2*C22
               + 2.f*(w0*w1*C01 + w0*w2*C02 + w1*w2*C12);
    float sc = gamma[c] * rsqrtf(var + 1e-5f);
    g_cw[c*3+0] = w0 * sc;
    g_cw[c*3+1] = w1 * sc;
    g_cw[c*3+2] = w2 * sc;
    g_cb[c]     = conv_b[c] * sc + (beta[c] - mean * sc);
}

// ---------------- kernel 3: persistent clustered LSTM ----------------
// 128 CTAs, cluster=(2,1,1): blockIdx.x>>1 = batch row, blockIdx.x&1 = hidden half.
// QUAD layout: q = tid&3 (gate i/f/g/o), jj = tid>>2 (hidden unit within half).
// The 4 gates of unit jj live in 4 ADJACENT LANES of one warp -> gate gather is
// 4 shfl (no smem/barrier); c lives in registers (quad-redundant).
// W_hh is split into SEPARATE compile-time-indexed register arrays (own/peer):
// the runtime half-offset is applied at the GMEM load address only, so the
// arrays stay register-resident (no dynamic register indexing -> no spills).
// Pre-wait work = bias + W_ih*y + W_hh_own*h_own (hides the exchange flight).
__global__ void __cluster_dims__(2, 1, 1) __launch_bounds__(256, 1)
lstm_kernel(const float* __restrict__ x,
            const float* __restrict__ w_ih, const float* __restrict__ b_ih,
            const float* __restrict__ w_hh, const float* __restrict__ b_hh,
            const float* __restrict__ out_w, const float* __restrict__ out_b,
            const float* __restrict__ h0, const float* __restrict__ c0,
            float* __restrict__ out) {
    __shared__ __align__(16) float h_s[2][H_];   // double-buffered full h
    __shared__ __align__(16) float y_s[C1_];     // conv/BN/relu output, current step
    __shared__ __align__(8) unsigned long long mbar[1];

    const int tid  = threadIdx.x;
    const int b    = blockIdx.x >> 1;
    const int half = blockIdx.x & 1;
    const int q    = tid & 3;         // gate: 0=i 1=f 2=g 3=o
    const int jj   = tid >> 2;        // hidden unit within half [0,64)
    const int r    = q * H_ + half * 64 + jj;   // global gate row in [0,512)
    const int lane = tid & 31;
    const int qb   = lane & ~3;       // quad base lane
    const int own_off  = half * 64;
    const int peer_off = own_off ^ 64;

    // pack weights: separate own/peer arrays, compile-time indexed (no spills)
    unsigned long long whh_own[32], whh_per[32];
    {
        const float2* wo = (const float2*)(w_hh + (size_t)r * H_ + own_off);
        const float2* wp = (const float2*)(w_hh + (size_t)r * H_ + peer_off);
        #pragma unroll
        for (int k = 0; k < 32; k++) {
            float2 a = wo[k]; whh_own[k] = pack2(a.x, a.y);
            float2 c = wp[k]; whh_per[k] = pack2(c.x, c.y);
        }
    }
    unsigned long long wih2[C1_ / 2];
    #pragma unroll
    for (int k = 0; k < C1_ / 2; k++) {
        float2 w = ((const float2*)(w_ih + (size_t)r * C1_))[k];
        wih2[k] = pack2(w.x, w.y);
    }
    const float bias = b_ih[r] + b_hh[r];
    // branchless activation constants: a = (1+m)/(1+exp(-s*a)) - m
    const float act_s = (q == 2) ? 2.f : 1.f;   // tanh uses exp(-2v)
    const float act_m = (q == 2) ? 1.f : 0.f;

    // state init: c replicated in all 4 lanes of the quad (registers only)
    float creg = c0[b * H_ + half * 64 + jj];
    if (tid < H_) h_s[0][tid] = h0[b * H_ + tid];

    const float* xb = x + (size_t)b * T_ * 3;
    if (q == 1) {   // y(0): 64 q==1 lanes, channel jj
        float v = fmaf(g_cw[jj*3+2], xb[2],
                  fmaf(g_cw[jj*3+1], xb[1],
                  fmaf(g_cw[jj*3+0], xb[0], g_cb[jj])));
        y_s[jj] = fmaxf(v, 0.f);
    }

    const uint32_t mbar_a    = smem_u32(mbar);
    const uint32_t peer_mbar = mapa_u32(mbar_a, (uint32_t)(half ^ 1));
    const uint32_t peer_h    = mapa_u32(smem_u32(&h_s[0][0]), (uint32_t)(half ^ 1));

    if (tid == 0) mbar_init(mbar_a, 1);
    __syncthreads();
    cluster_barrier();   // mbar init visible cluster-wide before any st.async
    if (tid == 0) mbar_expect_tx(mbar_a, 64 * 4);   // phase 0

    uint32_t parity = 0;
    const float* xp = xb + 3;

    #pragma unroll 1
    for (int t = 0; t < T_; t++) {
        const int cur = t & 1;
        // ---- pre-wait: bias + W_ih*y(t) + W_hh_own*h_own(t) (no peer dep) ----
        unsigned long long acc0 = pack2(bias, 0.f), acc1 = pack2(0.f, 0.f);
        const float4* y4 = (const float4*)y_s;
        #pragma unroll
        for (int c2 = 0; c2 < C1_ / 4; c2++) {
            F4U2 yv; yv.v = y4[c2];
            ffma2(acc0, wih2[2*c2],     yv.u[0]);
            ffma2(acc1, wih2[2*c2 + 1], yv.u[1]);
        }
        const float4* ho4 = (const float4*)&h_s[cur][own_off];
        #pragma unroll
        for (int k2 = 0; k2 < 16; k2++) {
            F4U2 hv; hv.v = ho4[k2];
            ffma2(acc0, whh_own[2*k2],     hv.u[0]);
            ffma2(acc1, whh_own[2*k2 + 1], hv.u[1]);
        }
        // prefetch x(t+1) for the conv lanes
        float px0 = 0.f, px1 = 0.f, px2 = 0.f;
        const bool doy = (q == 1) && (t < T_ - 1);
        if (doy) { px0 = xp[0]; px1 = xp[1]; px2 = xp[2]; }

        // ---- wait for peer half of h(t); re-arm for next phase ----
        if (t > 0) {
            mbar_wait(mbar_a, parity);
            parity ^= 1;
            if (tid == 0) mbar_expect_tx(mbar_a, 64 * 4);
        }
        const float4* hp4 = (const float4*)&h_s[cur][peer_off];
        #pragma unroll
        for (int k2 = 0; k2 < 16; k2++) {
            F4U2 hv; hv.v = hp4[k2];
            ffma2(acc0, whh_per[2*k2],     hv.u[0]);
            ffma2(acc1, whh_per[2*k2 + 1], hv.u[1]);
        }
        float l0, hh0, l1, hh1;
        unpack2(l0, hh0, acc0);
        unpack2(l1, hh1, acc1);
        float a = (l0 + l1) + (hh0 + hh1);
        // branchless sigmoid/tanh (single exp + divide for every lane)
        a = __fdividef(1.f + act_m, 1.f + __expf(-act_s * a)) - act_m;

        // ---- quad gate gather via shfl (same warp, adjacent lanes) ----
        float gi = __shfl_sync(0xFFFFFFFFu, a, qb + 0);
        float gf = __shfl_sync(0xFFFFFFFFu, a, qb + 1);
        float gg = __shfl_sync(0xFFFFFFFFu, a, qb + 2);
        float go = __shfl_sync(0xFFFFFFFFu, a, qb + 3);
        creg = fmaf(gf, creg, gi * gg);
        float hn = go * tanh_fast(creg);

        const int nxt = cur ^ 1;
        const int hj  = own_off + jj;
        if (q == 0) {
            h_s[nxt][hj] = hn;
            st_async_remote_f32(peer_h + (uint32_t)(nxt * H_ + hj) * 4u, hn, peer_mbar);
        } else if (doy) {
            float v = fmaf(g_cw[jj*3+2], px2,
                      fmaf(g_cw[jj*3+1], px1,
                      fmaf(g_cw[jj*3+0], px0, g_cb[jj])));
            y_s[jj] = fmaxf(v, 0.f);
        }
        __syncthreads();   // local h own-half + y(t+1) visibility for next step
        xp += 3;
    }

    // final: h(T) lands in buffer 0 (T even); wait for peer half
    mbar_wait(mbar_a, parity);

    if (half == 0 && tid < NCLS_) {
        float acc = out_b[tid];
        #pragma unroll 4
        for (int k = 0; k < H_; k++)
            acc = fmaf(h_s[0][k], out_w[tid * H_ + k], acc);
        out[b * NCLS_ + tid] = acc;
    }
    cluster_barrier();   // clean cluster teardown
}

// ---------------- launch ----------------
extern "C" void kernel_launch(void* const* d_in, const int* in_sizes, int n_in,
                              void* d_out, int out_size) {
    const float* x      = (const float*)d_in[0];
    const float* conv_w = (const float*)d_in[1];
    const float* conv_b = (const float*)d_in[2];
    const float* bn_g   = (const float*)d_in[3];
    const float* bn_b   = (const float*)d_in[4];
    const float* w_ih   = (const float*)d_in[5];
    const float* b_ih   = (const float*)d_in[6];
    const float* w_hh   = (const float*)d_in[7];
    const float* b_hh   = (const float*)d_in[8];
    const float* out_w  = (const float*)d_in[9];
    const float* out_b  = (const float*)d_in[10];
    const float* h0     = (const float*)d_in[11];
    const float* c0     = (const float*)d_in[12];
    float* out = (float*)d_out;

    stats_kernel<<<NSTAT_BLK, 256>>>(x);
    fold_kernel<<<1, 64>>>(conv_w, conv_b, bn_g, bn_b);
    lstm_kernel<<<2 * B_, 256>>>(x, w_ih, b_ih, w_hh, b_hh,
                                 out_w, out_b, h0, c0, out);
}